// round 13
// baseline (speedup 1.0000x reference)
#include <cuda_runtime.h>
#include <cuda_fp16.h>
#include <cstdint>

// S4 kernel materialization on HMMA (mma.sync m16n8k16 fp16):
//   K[h,l] = 2*Re( sum_n Cc_n z_n^l ),  z = exp(dtA), Cc = C*(z-1)/A
// l = 64q + r -> per-h GEMM D[64q][64r] = A[64x64] @ B[64x64]^T (K=64, j=2n re/im)
// Single fp16 product D = A*B, fp32 accum (rel_err ~2e-4).
// R13: per-n head computed ONCE by warp 0 (smem anchor broadcast);
//      B chains run conjugated with folded 2/-2 (no per-word scaling).

#define Hh   1024
#define NHn  32
#define Ll   4096

__device__ __forceinline__ uint32_t pack_h2(float re, float im) {
    __half2 v = __floats2half2_rn(re, im);   // low = re (k even), high = im (k odd)
    return *(uint32_t*)&v;
}

__device__ __forceinline__ void mma16816(float* c, const uint32_t* a,
                                         uint32_t b0, uint32_t b1) {
    asm volatile(
        "mma.sync.aligned.m16n8k16.row.col.f32.f16.f16.f32 "
        "{%0,%1,%2,%3}, {%4,%5,%6,%7}, {%8,%9}, {%0,%1,%2,%3};"
        : "+f"(c[0]), "+f"(c[1]), "+f"(c[2]), "+f"(c[3])
        : "r"(a[0]), "r"(a[1]), "r"(a[2]), "r"(a[3]), "r"(b0), "r"(b1));
}

__device__ __forceinline__ void ldmx4(uint32_t* r, uint32_t addr) {
    asm volatile(
        "ldmatrix.sync.aligned.m8n8.x4.shared.b16 {%0,%1,%2,%3}, [%4];"
        : "=r"(r[0]), "=r"(r[1]), "=r"(r[2]), "=r"(r[3]) : "r"(addr));
}

__global__ __launch_bounds__(128, 8)
void s4_hmma_kernel(const float* __restrict__ Cin,        // [H, NH, 2]
                    const float* __restrict__ log_dt,     // [H]
                    const float* __restrict__ log_A_real, // [H, NH]
                    const float* __restrict__ A_imag,     // [H, NH]
                    float* __restrict__ out)              // [H, L]
{
    // 64 rows x 32 words (64 fp16) per tile, XOR swizzle: word = n ^ ((row&7)<<2)
    __shared__ uint32_t At[64 * 32];
    __shared__ uint32_t Bt[64 * 32];
    // anchors: 0:z 1:z8 2:z16 3:z32 4:z48 5:z64 6:z512 7:z1024 8:z2048 9:z3072 10:Cc
    __shared__ float2 anch[11][NHn];

    const int h    = blockIdx.x;
    const int tid  = threadIdx.x;
    const int lane = tid & 31;
    const int w    = tid >> 5;

    // ---- phase 0: warp 0 computes the per-n head ONCE ----
    if (w == 0) {
        const int n = lane;
        float dt   = __expf(log_dt[h]);
        float Are  = -__expf(log_A_real[h * NHn + n]);
        float Aim  = -A_imag[h * NHn + n];
        float dtar = Are * dt;
        float dtai = Aim * dt;

        float er = __expf(dtar);
        float sn, cs;
        __sincosf(dtai, &sn, &cs);
        float zr = er * cs, zi = er * sn;            // z = exp(dtA)

        // Cc = C * (z-1)/A
        float nr = zr - 1.0f, ni = zi;
        float inv = __fdividef(1.0f, Are * Are + Aim * Aim);
        float fr = (nr * Are + ni * Aim) * inv;
        float fi = (ni * Are - nr * Aim) * inv;
        float c0 = Cin[(h * NHn + n) * 2 + 0];
        float c1 = Cin[(h * NHn + n) * 2 + 1];
        float ccr = c0 * fr - c1 * fi;
        float cci = c0 * fi + c1 * fr;

        #define CSQ(r_, i_) { float t_ = r_*r_ - i_*i_; i_ = 2.0f*r_*i_; r_ = t_; }
        float z8r = zr, z8i = zi;
        CSQ(z8r, z8i) CSQ(z8r, z8i) CSQ(z8r, z8i)                 // z^8
        float z16r = z8r, z16i = z8i;   CSQ(z16r, z16i)           // z^16
        float z32r = z16r, z32i = z16i; CSQ(z32r, z32i)           // z^32
        float z48r = z16r * z32r - z16i * z32i;                   // z^48
        float z48i = z16r * z32i + z16i * z32r;
        float z64r = z32r, z64i = z32i; CSQ(z64r, z64i)           // z^64
        float z512r = z64r, z512i = z64i;
        CSQ(z512r, z512i) CSQ(z512r, z512i) CSQ(z512r, z512i)     // z^512
        float z1024r = z512r, z1024i = z512i; CSQ(z1024r, z1024i) // z^1024
        float z2048r = z1024r, z2048i = z1024i; CSQ(z2048r, z2048i) // z^2048
        float z3072r = z1024r * z2048r - z1024i * z2048i;         // z^3072
        float z3072i = z1024r * z2048i + z1024i * z2048r;
        #undef CSQ

        anch[0][n]  = make_float2(zr, zi);
        anch[1][n]  = make_float2(z8r, z8i);
        anch[2][n]  = make_float2(z16r, z16i);
        anch[3][n]  = make_float2(z32r, z32i);
        anch[4][n]  = make_float2(z48r, z48i);
        anch[5][n]  = make_float2(z64r, z64i);
        anch[6][n]  = make_float2(z512r, z512i);
        anch[7][n]  = make_float2(z1024r, z1024i);
        anch[8][n]  = make_float2(z2048r, z2048i);
        anch[9][n]  = make_float2(z3072r, z3072i);
        anch[10][n] = make_float2(ccr, cci);
    }
    __syncthreads();

    // ---- phase 1: 4 chains x 8 steps per warp from broadcast anchors ----
    {
        const int n = lane;
        float2 z    = anch[0][n];
        float2 z8   = anch[1][n];
        float2 z64  = anch[5][n];
        float2 z512 = anch[6][n];
        float2 cc   = anch[10][n];
        float2 pw   = (w == 0) ? make_float2(1.f, 0.f) : anch[w + 1][n];  // z^(16w)
        float2 aw   = (w == 0) ? make_float2(1.f, 0.f) : anch[w + 6][n];  // z^(1024w)

        // B chains conjugated: s_r = 2*conj(Cc z^r); step conj(z)
        float ur  = cc.x * pw.x - cc.y * pw.y;       // Cc * z^(16w)
        float ui  = cc.x * pw.y + cc.y * pw.x;
        float s0r = 2.0f * ur,  s0i = -2.0f * ui;
        float s1r = s0r * z8.x + s0i * z8.y;         // * conj(z8)
        float s1i = s0i * z8.x - s0r * z8.y;
        const float bzr = z.x, bzi = -z.y;           // conj(z)

        // A chains: t_q = z^(64q); step z64
        float t0r = aw.x, t0i = aw.y;
        float t1r = aw.x * z512.x - aw.y * z512.y;
        float t1i = aw.x * z512.y + aw.y * z512.x;

        const int base = w * 16 * 32;                // row-major word base

        #pragma unroll
        for (int i = 0; i < 8; i++) {
            int wo0 = base + i * 32 + (n ^ (i << 2));    // row 16w+i  (&7 == i)
            int wo1 = wo0 + 8 * 32;                      // row 16w+8+i
            Bt[wo0] = pack_h2(s0r, s0i);
            Bt[wo1] = pack_h2(s1r, s1i);
            At[wo0] = pack_h2(t0r, t0i);
            At[wo1] = pack_h2(t1r, t1i);

            float t;
            t = s0r * bzr - s0i * bzi;      s0i = s0r * bzi + s0i * bzr;      s0r = t;
            t = s1r * bzr - s1i * bzi;      s1i = s1r * bzi + s1i * bzr;      s1r = t;
            t = t0r * z64.x - t0i * z64.y;  t0i = t0r * z64.y + t0i * z64.x;  t0r = t;
            t = t1r * z64.x - t1i * z64.y;  t1i = t1r * z64.y + t1i * z64.x;  t1r = t;
        }
    }
    __syncthreads();

    // ---- phase 2: MMA with ldmatrix fragment loads (verified R12 layout) ----
    const int lane8 = lane & 7;
    const int g     = lane >> 3;          // ldmatrix matrix-group 0..3
    const uint32_t swx = (uint32_t)lane8 << 2;

    uint32_t aBase = (uint32_t)__cvta_generic_to_shared(At);
    uint32_t bBase = (uint32_t)__cvta_generic_to_shared(Bt);

    const uint32_t aRow  = (uint32_t)(w * 16 + ((g & 1) << 3) + lane8);
    const uint32_t aOff0 = (aRow << 5) << 2;
    const uint32_t aKsel = (uint32_t)((g >> 1) << 2);

    const uint32_t bKsel = (uint32_t)((g & 1) << 2);
    uint32_t bOff0[4];
    #pragma unroll
    for (int p = 0; p < 4; p++) {
        uint32_t nt0 = (uint32_t)(2 * p + (g >> 1));
        uint32_t row = (nt0 << 3) + (uint32_t)lane8;
        bOff0[p] = (row << 5) << 2;
    }

    float acc[8][4];
    #pragma unroll
    for (int nt = 0; nt < 8; nt++)
        #pragma unroll
        for (int i = 0; i < 4; i++) acc[nt][i] = 0.0f;

    #pragma unroll
    for (int ks = 0; ks < 4; ks++) {
        uint32_t aw_ = (uint32_t)(ks * 8) + aKsel;
        uint32_t aoff = aOff0 + ((aw_ ^ swx) << 2);
        uint32_t a[4];
        ldmx4(a, aBase + aoff);

        uint32_t wc  = (uint32_t)(ks * 8) + bKsel;
        uint32_t wcs = (wc ^ swx) << 2;

        uint32_t b[8];
        ldmx4(&b[0], bBase + bOff0[0] + wcs);
        ldmx4(&b[4], bBase + bOff0[1] + wcs);
        #pragma unroll
        for (int nt = 0; nt < 4; nt++)
            mma16816(acc[nt], a, b[nt * 2], b[nt * 2 + 1]);

        ldmx4(&b[0], bBase + bOff0[2] + wcs);
        ldmx4(&b[4], bBase + bOff0[3] + wcs);
        #pragma unroll
        for (int nt = 0; nt < 4; nt++)
            mma16816(acc[4 + nt], a, b[nt * 2], b[nt * 2 + 1]);
    }

    // ---- epilogue: D(q, r) -> out[h, 64q + r] ----
    const int lane4 = lane >> 2;
    const int kq    = lane & 3;
    const int q0 = w * 16 + lane4, q1 = q0 + 8;
    const int cb = kq * 2;
    float* o = out + (size_t)h * Ll;
    #pragma unroll
    for (int nt = 0; nt < 8; nt++) {
        int c = nt * 8 + cb;
        *(float2*)&o[q0 * 64 + c] = make_float2(acc[nt][0], acc[nt][1]);
        *(float2*)&o[q1 * 64 + c] = make_float2(acc[nt][2], acc[nt][3]);
    }
}

extern "C" void kernel_launch(void* const* d_in, const int* in_sizes, int n_in,
                              void* d_out, int out_size)
{
    const float* C          = (const float*)d_in[0];   // [H, NH, 2]
    const float* log_dt     = (const float*)d_in[1];   // [H]
    const float* log_A_real = (const float*)d_in[2];   // [H, NH]
    const float* A_imag     = (const float*)d_in[3];   // [H, NH]
    float* out              = (float*)d_out;           // [H, L]

    s4_hmma_kernel<<<Hh, 128>>>(C, log_dt, log_A_real, A_imag, out);
}

// round 14
// speedup vs baseline: 1.0029x; 1.0029x over previous
#include <cuda_runtime.h>
#include <cuda_fp16.h>
#include <cstdint>

// S4 kernel materialization on HMMA (mma.sync m16n8k16 fp16):
//   K[h,l] = 2*Re( sum_n Cc_n z_n^l ),  z = exp(dtA), Cc = C*(z-1)/A
// l = 64q + r -> per-h GEMM D[64q][64r] = A[64x64] @ B[64x64]^T (K=64, j=2n re/im)
// Single fp16 product, fp32 accum (rel_err ~2e-4).
// R14: 2 heads per CTA, double-buffered tiles; phase-1 chains of h1 are
// interleaved with the MMA of h0 to fill latency gaps inside each warp.

#define Hh   1024
#define NHn  32
#define Ll   4096
#define TW   2048          // tile words (64 rows x 32 words)

__device__ __forceinline__ uint32_t pack_h2(float re, float im) {
    __half2 v = __floats2half2_rn(re, im);
    return *(uint32_t*)&v;
}

__device__ __forceinline__ void mma16816(float* c, const uint32_t* a,
                                         uint32_t b0, uint32_t b1) {
    asm volatile(
        "mma.sync.aligned.m16n8k16.row.col.f32.f16.f16.f32 "
        "{%0,%1,%2,%3}, {%4,%5,%6,%7}, {%8,%9}, {%0,%1,%2,%3};"
        : "+f"(c[0]), "+f"(c[1]), "+f"(c[2]), "+f"(c[3])
        : "r"(a[0]), "r"(a[1]), "r"(a[2]), "r"(a[3]), "r"(b0), "r"(b1));
}

__device__ __forceinline__ void ldmx4(uint32_t* r, uint32_t addr) {
    asm volatile(
        "ldmatrix.sync.aligned.m8n8.x4.shared.b16 {%0,%1,%2,%3}, [%4];"
        : "=r"(r[0]), "=r"(r[1]), "=r"(r[2]), "=r"(r[3]) : "r"(addr));
}

struct Chains {
    float s0r, s0i, s1r, s1i;    // B rows (conjugated, 2/-2 folded)
    float t0r, t0i, t1r, t1i;    // A rows
    float bzr, bzi, z64r, z64i;  // steps
};

__device__ __forceinline__ Chains make_chains(
    const float* __restrict__ Cin, const float* __restrict__ log_dt,
    const float* __restrict__ lAr, const float* __restrict__ Aimg,
    int h, int n, int w)
{
    float dt   = __expf(log_dt[h]);
    float Are  = -__expf(lAr[h * NHn + n]);
    float Aim  = -Aimg[h * NHn + n];
    float dtar = Are * dt;
    float dtai = Aim * dt;

    float er = __expf(dtar);
    float sn, cs;
    __sincosf(dtai, &sn, &cs);
    float zr = er * cs, zi = er * sn;            // z = exp(dtA)

    float nr = zr - 1.0f, ni = zi;
    float inv = __fdividef(1.0f, Are * Are + Aim * Aim);
    float fr = (nr * Are + ni * Aim) * inv;
    float fi = (ni * Are - nr * Aim) * inv;
    float c0 = Cin[(h * NHn + n) * 2 + 0];
    float c1 = Cin[(h * NHn + n) * 2 + 1];
    float ccr = c0 * fr - c1 * fi;
    float cci = c0 * fi + c1 * fr;

    #define CSQ(r_, i_) { float t_ = r_*r_ - i_*i_; i_ = 2.0f*r_*i_; r_ = t_; }
    float z8r = zr, z8i = zi;
    CSQ(z8r, z8i) CSQ(z8r, z8i) CSQ(z8r, z8i)               // z^8
    float z16r = z8r, z16i = z8i;   CSQ(z16r, z16i)         // z^16
    float z32r = z16r, z32i = z16i; CSQ(z32r, z32i)         // z^32
    float z64r = z32r, z64i = z32i; CSQ(z64r, z64i)         // z^64
    float z512r = z64r, z512i = z64i;
    CSQ(z512r, z512i) CSQ(z512r, z512i) CSQ(z512r, z512i)   // z^512
    float z1024r = z512r, z1024i = z512i; CSQ(z1024r, z1024i)
    float z2048r = z1024r, z2048i = z1024i; CSQ(z2048r, z2048i)
    #undef CSQ

    // z^(16w)
    float pwr, pwi;
    if (w == 0)      { pwr = 1.0f;  pwi = 0.0f;  }
    else if (w == 1) { pwr = z16r;  pwi = z16i;  }
    else if (w == 2) { pwr = z32r;  pwi = z32i;  }
    else             { pwr = z16r * z32r - z16i * z32i;
                       pwi = z16r * z32i + z16i * z32r; }
    // z^(1024w)
    float awr, awi;
    if (w == 0)      { awr = 1.0f;   awi = 0.0f;   }
    else if (w == 1) { awr = z1024r; awi = z1024i; }
    else if (w == 2) { awr = z2048r; awi = z2048i; }
    else             { awr = z1024r * z2048r - z1024i * z2048i;
                       awi = z1024r * z2048i + z1024i * z2048r; }

    Chains c;
    // B chains conjugated with folded 2/-2: s_r = 2*conj(Cc z^r), step conj(z)
    float ur = ccr * pwr - cci * pwi;
    float ui = ccr * pwi + cci * pwr;
    c.s0r = 2.0f * ur;  c.s0i = -2.0f * ui;
    c.s1r = c.s0r * z8r + c.s0i * z8i;           // * conj(z8)
    c.s1i = c.s0i * z8r - c.s0r * z8i;
    c.bzr = zr; c.bzi = -zi;
    // A chains
    c.t0r = awr; c.t0i = awi;
    c.t1r = awr * z512r - awi * z512i;
    c.t1i = awr * z512i + awi * z512r;
    c.z64r = z64r; c.z64i = z64i;
    return c;
}

// one chain iteration: store rows (16w+i, 16w+8+i) in both tiles, advance
__device__ __forceinline__ void chain_step(Chains& c, uint32_t* At, uint32_t* Bt,
                                           int wbase, int n, int i)
{
    int wo0 = wbase + i * 32 + (n ^ (i << 2));
    int wo1 = wo0 + 256;
    Bt[wo0] = pack_h2(c.s0r, c.s0i);
    Bt[wo1] = pack_h2(c.s1r, c.s1i);
    At[wo0] = pack_h2(c.t0r, c.t0i);
    At[wo1] = pack_h2(c.t1r, c.t1i);
    float t;
    t = c.s0r * c.bzr - c.s0i * c.bzi;   c.s0i = c.s0r * c.bzi + c.s0i * c.bzr;   c.s0r = t;
    t = c.s1r * c.bzr - c.s1i * c.bzi;   c.s1i = c.s1r * c.bzi + c.s1i * c.bzr;   c.s1r = t;
    t = c.t0r * c.z64r - c.t0i * c.z64i; c.t0i = c.t0r * c.z64i + c.t0i * c.z64r; c.t0r = t;
    t = c.t1r * c.z64r - c.t1i * c.z64i; c.t1i = c.t1r * c.z64i + c.t1i * c.z64r; c.t1r = t;
}

__global__ __launch_bounds__(128, 6)
void s4_hmma_kernel(const float* __restrict__ Cin,        // [H, NH, 2]
                    const float* __restrict__ log_dt,     // [H]
                    const float* __restrict__ log_A_real, // [H, NH]
                    const float* __restrict__ A_imag,     // [H, NH]
                    float* __restrict__ out)              // [H, L]
{
    __shared__ uint32_t At[2][TW];
    __shared__ uint32_t Bt[2][TW];

    const int h0   = blockIdx.x * 2;
    const int h1   = h0 + 1;
    const int tid  = threadIdx.x;
    const int lane = tid & 31;
    const int w    = tid >> 5;
    const int n    = lane;
    const int wbase = w * 512;                    // w*16 rows * 32 words

    // ---- phase 1 for h0 into buffer 0 ----
    {
        Chains c0 = make_chains(Cin, log_dt, log_A_real, A_imag, h0, n, w);
        #pragma unroll
        for (int i = 0; i < 8; i++)
            chain_step(c0, At[0], Bt[0], wbase, n, i);
    }
    __syncthreads();

    // ---- MMA offsets (buffer-relative, verified R12 layout) ----
    const int lane8 = lane & 7;
    const int g     = lane >> 3;
    const uint32_t swx = (uint32_t)lane8 << 2;
    uint32_t aBase0 = (uint32_t)__cvta_generic_to_shared(&At[0][0]);
    uint32_t bBase0 = (uint32_t)__cvta_generic_to_shared(&Bt[0][0]);

    const uint32_t aRow  = (uint32_t)(w * 16 + ((g & 1) << 3) + lane8);
    const uint32_t aOff0 = (aRow << 5) << 2;
    const uint32_t aKsel = (uint32_t)((g >> 1) << 2);
    const uint32_t bKsel = (uint32_t)((g & 1) << 2);
    uint32_t bOff0[4];
    #pragma unroll
    for (int p = 0; p < 4; p++) {
        uint32_t nt0 = (uint32_t)(2 * p + (g >> 1));
        uint32_t row = (nt0 << 3) + (uint32_t)lane8;
        bOff0[p] = (row << 5) << 2;
    }

    float acc[8][4];
    #pragma unroll
    for (int nt = 0; nt < 8; nt++)
        #pragma unroll
        for (int i = 0; i < 4; i++) acc[nt][i] = 0.0f;

    // ---- interleaved: head+chains(h1 -> buffer 1)  |  MMA(h0 from buffer 0) ----
    Chains c1 = make_chains(Cin, log_dt, log_A_real, A_imag, h1, n, w);

    #pragma unroll
    for (int ks = 0; ks < 4; ks++) {
        // two chain steps for h1 (independent of the MMA below)
        chain_step(c1, At[1], Bt[1], wbase, n, 2 * ks);
        chain_step(c1, At[1], Bt[1], wbase, n, 2 * ks + 1);

        // MMA chunk ks for h0
        uint32_t aw_  = (uint32_t)(ks * 8) + aKsel;
        uint32_t aoff = aOff0 + ((aw_ ^ swx) << 2);
        uint32_t a[4];
        ldmx4(a, aBase0 + aoff);

        uint32_t wc  = (uint32_t)(ks * 8) + bKsel;
        uint32_t wcs = (wc ^ swx) << 2;
        uint32_t b[8];
        ldmx4(&b[0], bBase0 + bOff0[0] + wcs);
        ldmx4(&b[4], bBase0 + bOff0[1] + wcs);
        #pragma unroll
        for (int nt = 0; nt < 4; nt++)
            mma16816(acc[nt], a, b[nt * 2], b[nt * 2 + 1]);
        ldmx4(&b[0], bBase0 + bOff0[2] + wcs);
        ldmx4(&b[4], bBase0 + bOff0[3] + wcs);
        #pragma unroll
        for (int nt = 0; nt < 4; nt++)
            mma16816(acc[4 + nt], a, b[nt * 2], b[nt * 2 + 1]);
    }

    // ---- epilogue h0 (register-only, before the barrier) ----
    const int lane4 = lane >> 2;
    const int kq    = lane & 3;
    const int q0 = w * 16 + lane4, q1 = q0 + 8;
    const int cb = kq * 2;
    {
        float* o = out + (size_t)h0 * Ll;
        #pragma unroll
        for (int nt = 0; nt < 8; nt++) {
            int cc = nt * 8 + cb;
            *(float2*)&o[q0 * 64 + cc] = make_float2(acc[nt][0], acc[nt][1]);
            *(float2*)&o[q1 * 64 + cc] = make_float2(acc[nt][2], acc[nt][3]);
        }
    }
    __syncthreads();

    // ---- MMA + epilogue for h1 from buffer 1 ----
    uint32_t aBase1 = aBase0 + TW * 4;
    uint32_t bBase1 = bBase0 + TW * 4;

    #pragma unroll
    for (int nt = 0; nt < 8; nt++)
        #pragma unroll
        for (int i = 0; i < 4; i++) acc[nt][i] = 0.0f;

    #pragma unroll
    for (int ks = 0; ks < 4; ks++) {
        uint32_t aw_  = (uint32_t)(ks * 8) + aKsel;
        uint32_t aoff = aOff0 + ((aw_ ^ swx) << 2);
        uint32_t a[4];
        ldmx4(a, aBase1 + aoff);

        uint32_t wc  = (uint32_t)(ks * 8) + bKsel;
        uint32_t wcs = (wc ^ swx) << 2;
        uint32_t b[8];
        ldmx4(&b[0], bBase1 + bOff0[0] + wcs);
        ldmx4(&b[4], bBase1 + bOff0[1] + wcs);
        #pragma unroll
        for (int nt = 0; nt < 4; nt++)
            mma16816(acc[nt], a, b[nt * 2], b[nt * 2 + 1]);
        ldmx4(&b[0], bBase1 + bOff0[2] + wcs);
        ldmx4(&b[4], bBase1 + bOff0[3] + wcs);
        #pragma unroll
        for (int nt = 0; nt < 4; nt++)
            mma16816(acc[4 + nt], a, b[nt * 2], b[nt * 2 + 1]);
    }

    {
        float* o = out + (size_t)h1 * Ll;
        #pragma unroll
        for (int nt = 0; nt < 8; nt++) {
            int cc = nt * 8 + cb;
            *(float2*)&o[q0 * 64 + cc] = make_float2(acc[nt][0], acc[nt][1]);
            *(float2*)&o[q1 * 64 + cc] = make_float2(acc[nt][2], acc[nt][3]);
        }
    }
}

extern "C" void kernel_launch(void* const* d_in, const int* in_sizes, int n_in,
                              void* d_out, int out_size)
{
    const float* C          = (const float*)d_in[0];   // [H, NH, 2]
    const float* log_dt     = (const float*)d_in[1];   // [H]
    const float* log_A_real = (const float*)d_in[2];   // [H, NH]
    const float* A_imag     = (const float*)d_in[3];   // [H, NH]
    float* out              = (float*)d_out;           // [H, L]

    s4_hmma_kernel<<<Hh / 2, 128>>>(C, log_dt, log_A_real, A_imag, out);
}

// round 15
// speedup vs baseline: 1.2657x; 1.2620x over previous
#include <cuda_runtime.h>
#include <cuda_fp16.h>
#include <cstdint>

// S4 kernel materialization on HMMA (mma.sync m16n8k16 fp16):
//   K[h,l] = 2*Re( sum_n Cc_n z_n^l ),  z = exp(dtA), Cc = C*(z-1)/A
// l = 64q + r -> per-h GEMM D[64q][64r] = A[64x64] @ B[64x64]^T (K=64, j=2n re/im)
// Single fp16 product, fp32 accum (rel_err ~2e-4).
// R15 = R12 structure + direct-exponential anchors (no serial squaring chain):
//   z^k = __expf(k*dtar) * cis(k*dtai), all anchors independent.
//   Large-k sincos range-reduction error is suppressed by exp decay
//   (|dtai/dtar| <= ~25 bounds phase-error-at-visible-magnitude to ~1e-5).

#define Hh   1024
#define NHn  32
#define Ll   4096

__device__ __forceinline__ uint32_t pack_h2(float re, float im) {
    __half2 v = __floats2half2_rn(re, im);   // low = re (k even), high = im (k odd)
    return *(uint32_t*)&v;
}

__device__ __forceinline__ void mma16816(float* c, const uint32_t* a,
                                         uint32_t b0, uint32_t b1) {
    asm volatile(
        "mma.sync.aligned.m16n8k16.row.col.f32.f16.f16.f32 "
        "{%0,%1,%2,%3}, {%4,%5,%6,%7}, {%8,%9}, {%0,%1,%2,%3};"
        : "+f"(c[0]), "+f"(c[1]), "+f"(c[2]), "+f"(c[3])
        : "r"(a[0]), "r"(a[1]), "r"(a[2]), "r"(a[3]), "r"(b0), "r"(b1));
}

__device__ __forceinline__ void ldmx4(uint32_t* r, uint32_t addr) {
    asm volatile(
        "ldmatrix.sync.aligned.m8n8.x4.shared.b16 {%0,%1,%2,%3}, [%4];"
        : "=r"(r[0]), "=r"(r[1]), "=r"(r[2]), "=r"(r[3]) : "r"(addr));
}

// z^k scaled: returns mag*exp(k*dtar) * cis(k*dtai)
__device__ __forceinline__ float2 zpow(float k, float dtar, float dtai) {
    float er = __expf(k * dtar);
    float sn, cs;
    __sincosf(k * dtai, &sn, &cs);
    return make_float2(er * cs, er * sn);
}

__global__ __launch_bounds__(128, 8)
void s4_hmma_kernel(const float* __restrict__ Cin,        // [H, NH, 2]
                    const float* __restrict__ log_dt,     // [H]
                    const float* __restrict__ log_A_real, // [H, NH]
                    const float* __restrict__ A_imag,     // [H, NH]
                    float* __restrict__ out)              // [H, L]
{
    // 64 rows x 32 words (64 fp16) per tile, XOR swizzle: word = n ^ ((row&7)<<2)
    __shared__ uint32_t At[64 * 32];
    __shared__ uint32_t Bt[64 * 32];

    const int h    = blockIdx.x;
    const int tid  = threadIdx.x;
    const int lane = tid & 31;
    const int w    = tid >> 5;

    // ---- phase 1: direct-exp anchors + 4 chains x 8 steps per warp ----
    {
        const int n = lane;

        float dt   = __expf(log_dt[h]);
        float Are  = -__expf(log_A_real[h * NHn + n]);
        float Aim  = -A_imag[h * NHn + n];
        float dtar = Are * dt;
        float dtai = Aim * dt;

        // independent anchors (no serial squaring)
        float2 z   = zpow(1.0f, dtar, dtai);                       // z
        float2 z64 = zpow(64.0f, dtar, dtai);                      // z^64
        float2 p0  = zpow((float)(16 * w),        dtar, dtai);     // z^(16w)
        float2 p1  = zpow((float)(16 * w + 8),    dtar, dtai);     // z^(16w+8)
        float2 a0  = zpow((float)(1024 * w),       dtar, dtai);    // z^(1024w)
        float2 a1  = zpow((float)(1024 * w + 512), dtar, dtai);    // z^(1024w+512)

        // Cc = C * (z-1)/A
        float nr = z.x - 1.0f, ni = z.y;
        float inv = __fdividef(1.0f, Are * Are + Aim * Aim);
        float fr = (nr * Are + ni * Aim) * inv;
        float fi = (ni * Are - nr * Aim) * inv;
        float c0 = Cin[(h * NHn + n) * 2 + 0];
        float c1 = Cin[(h * NHn + n) * 2 + 1];
        float ccr = c0 * fr - c1 * fi;
        float cci = c0 * fi + c1 * fr;

        // B chains conjugated with folded 2/-2: s_r = 2*conj(Cc z^r), step conj(z)
        float u0r = ccr * p0.x - cci * p0.y;
        float u0i = ccr * p0.y + cci * p0.x;
        float s0r = 2.0f * u0r, s0i = -2.0f * u0i;
        float u1r = ccr * p1.x - cci * p1.y;
        float u1i = ccr * p1.y + cci * p1.x;
        float s1r = 2.0f * u1r, s1i = -2.0f * u1i;
        const float bzr = z.x, bzi = -z.y;           // conj(z)

        // A chains: t = z^(64q), step z^64
        float t0r = a0.x, t0i = a0.y;
        float t1r = a1.x, t1i = a1.y;

        const int base = w * 512;                    // w*16 rows * 32 words

        #pragma unroll
        for (int i = 0; i < 8; i++) {
            int wo0 = base + i * 32 + (n ^ (i << 2));    // row 16w+i   (&7 == i)
            int wo1 = wo0 + 256;                         // row 16w+8+i
            Bt[wo0] = pack_h2(s0r, s0i);
            Bt[wo1] = pack_h2(s1r, s1i);
            At[wo0] = pack_h2(t0r, t0i);
            At[wo1] = pack_h2(t1r, t1i);

            float t;
            t = s0r * bzr - s0i * bzi;      s0i = s0r * bzi + s0i * bzr;      s0r = t;
            t = s1r * bzr - s1i * bzi;      s1i = s1r * bzi + s1i * bzr;      s1r = t;
            t = t0r * z64.x - t0i * z64.y;  t0i = t0r * z64.y + t0i * z64.x;  t0r = t;
            t = t1r * z64.x - t1i * z64.y;  t1i = t1r * z64.y + t1i * z64.x;  t1r = t;
        }
    }
    __syncthreads();

    // ---- phase 2: MMA with ldmatrix fragment loads (verified R12 layout) ----
    const int lane8 = lane & 7;
    const int g     = lane >> 3;          // ldmatrix matrix-group 0..3
    const uint32_t swx = (uint32_t)lane8 << 2;

    uint32_t aBase = (uint32_t)__cvta_generic_to_shared(At);
    uint32_t bBase = (uint32_t)__cvta_generic_to_shared(Bt);

    const uint32_t aRow  = (uint32_t)(w * 16 + ((g & 1) << 3) + lane8);
    const uint32_t aOff0 = (aRow << 5) << 2;
    const uint32_t aKsel = (uint32_t)((g >> 1) << 2);

    const uint32_t bKsel = (uint32_t)((g & 1) << 2);
    uint32_t bOff0[4];
    #pragma unroll
    for (int p = 0; p < 4; p++) {
        uint32_t nt0 = (uint32_t)(2 * p + (g >> 1));
        uint32_t row = (nt0 << 3) + (uint32_t)lane8;
        bOff0[p] = (row << 5) << 2;
    }

    float acc[8][4];
    #pragma unroll
    for (int nt = 0; nt < 8; nt++)
        #pragma unroll
        for (int i = 0; i < 4; i++) acc[nt][i] = 0.0f;

    #pragma unroll
    for (int ks = 0; ks < 4; ks++) {
        uint32_t aw_  = (uint32_t)(ks * 8) + aKsel;
        uint32_t aoff = aOff0 + ((aw_ ^ swx) << 2);
        uint32_t a[4];
        ldmx4(a, aBase + aoff);

        uint32_t wc  = (uint32_t)(ks * 8) + bKsel;
        uint32_t wcs = (wc ^ swx) << 2;

        uint32_t b[8];
        ldmx4(&b[0], bBase + bOff0[0] + wcs);
        ldmx4(&b[4], bBase + bOff0[1] + wcs);
        #pragma unroll
        for (int nt = 0; nt < 4; nt++)
            mma16816(acc[nt], a, b[nt * 2], b[nt * 2 + 1]);

        ldmx4(&b[0], bBase + bOff0[2] + wcs);
        ldmx4(&b[4], bBase + bOff0[3] + wcs);
        #pragma unroll
        for (int nt = 0; nt < 4; nt++)
            mma16816(acc[4 + nt], a, b[nt * 2], b[nt * 2 + 1]);
    }

    // ---- epilogue: D(q, r) -> out[h, 64q + r] ----
    const int lane4 = lane >> 2;
    const int kq    = lane & 3;
    const int q0 = w * 16 + lane4, q1 = q0 + 8;
    const int cb = kq * 2;
    float* o = out + (size_t)h * Ll;
    #pragma unroll
    for (int nt = 0; nt < 8; nt++) {
        int c = nt * 8 + cb;
        *(float2*)&o[q0 * 64 + c] = make_float2(acc[nt][0], acc[nt][1]);
        *(float2*)&o[q1 * 64 + c] = make_float2(acc[nt][2], acc[nt][3]);
    }
}

extern "C" void kernel_launch(void* const* d_in, const int* in_sizes, int n_in,
                              void* d_out, int out_size)
{
    const float* C          = (const float*)d_in[0];   // [H, NH, 2]
    const float* log_dt     = (const float*)d_in[1];   // [H]
    const float* log_A_real = (const float*)d_in[2];   // [H, NH]
    const float* A_imag     = (const float*)d_in[3];   // [H, NH]
    float* out              = (float*)d_out;           // [H, L]

    s4_hmma_kernel<<<Hh, 128>>>(C, log_dt, log_A_real, A_imag, out);
}